// round 4
// baseline (speedup 1.0000x reference)
#include <cuda_runtime.h>
#include <math.h>

// Problem constants
#define B    64
#define S    1024
#define D    512
#define H    512
#define G    2048      // 4*H
#define WROW 1024      // D+H, row stride of W
#define NCTA 128       // persistent CTAs (<=148 SMs, 1/SM guaranteed resident)
#define NTHR 256

// ---------------------------------------------------------------------------
// Scratch (__device__ globals: the sanctioned alloc-free workaround)
// ---------------------------------------------------------------------------
__device__ float g_xg[(size_t)S * B * G];   // 512 MB: input gates, layout (S, B, G)
__device__ float g_y1[(size_t)B * S * H];   // 128 MB: layer-1 output, layout (B, S, H)
__device__ float g_h[2][B * H];             // ping-pong hidden state
__device__ unsigned g_bar[2];               // grid-barrier counters (per layer)

// ---------------------------------------------------------------------------
// GEMM: xg[m][n] = sum_k A[m][k] * Wx[n][k] + bias[n];  m = t*B + b
// 128x128x16 tile, 8x8 per thread, 256 threads. Also zeroes g_bar[layer].
// ---------------------------------------------------------------------------
#define BM 128
#define BN 128
#define BK 16

__global__ void __launch_bounds__(256) gemm_xw(
    const float* __restrict__ Aext, int layer,
    const float* __restrict__ Wx,      // row stride WROW
    const float* __restrict__ bias)    // length G
{
    if (blockIdx.x == 0 && blockIdx.y == 0 && threadIdx.x == 0)
        g_bar[layer] = 0u;             // reset barrier for this layer's persistent kernel

    const float* A = layer ? g_y1 : Aext;
    const int n0 = blockIdx.x * BN;
    const int m0 = blockIdx.y * BM;

    __shared__ float As[BK][BM];
    __shared__ float Bs[BK][BN];

    const int tid = threadIdx.x;
    const int lr = tid >> 2;            // 0..63
    const int lc = (tid & 3) * 4;       // 0,4,8,12
    const int thrRow = (tid >> 4) * 8;
    const int thrCol = (tid & 15) * 8;

    float acc[8][8];
#pragma unroll
    for (int i = 0; i < 8; i++)
#pragma unroll
        for (int j = 0; j < 8; j++) acc[i][j] = 0.0f;

    for (int k0 = 0; k0 < D; k0 += BK) {
#pragma unroll
        for (int half = 0; half < 2; half++) {
            const int r = lr + half * 64;
            const int m = m0 + r;
            // A row for m = t*B + b lives at b*(S*512) + t*512
            const float* ap = A + (size_t)(m & (B - 1)) * ((size_t)S * 512)
                                + (size_t)(m >> 6) * 512 + k0 + lc;
            const float4 va = *reinterpret_cast<const float4*>(ap);
            As[lc + 0][r] = va.x;
            As[lc + 1][r] = va.y;
            As[lc + 2][r] = va.z;
            As[lc + 3][r] = va.w;

            const int n = n0 + r;
            const float4 vb = *reinterpret_cast<const float4*>(
                Wx + (size_t)n * WROW + k0 + lc);
            Bs[lc + 0][r] = vb.x;
            Bs[lc + 1][r] = vb.y;
            Bs[lc + 2][r] = vb.z;
            Bs[lc + 3][r] = vb.w;
        }
        __syncthreads();

#pragma unroll
        for (int k = 0; k < BK; k++) {
            float rm[8], rn[8];
#pragma unroll
            for (int i = 0; i < 8; i++) rm[i] = As[k][thrRow + i];
#pragma unroll
            for (int j = 0; j < 8; j++) rn[j] = Bs[k][thrCol + j];
#pragma unroll
            for (int i = 0; i < 8; i++)
#pragma unroll
                for (int j = 0; j < 8; j++)
                    acc[i][j] += rm[i] * rn[j];
        }
        __syncthreads();
    }

    float bb[8];
#pragma unroll
    for (int j = 0; j < 8; j++) bb[j] = bias[n0 + thrCol + j];

#pragma unroll
    for (int i = 0; i < 8; i++) {
        const size_t m = (size_t)(m0 + thrRow + i);
        float* cp = g_xg + m * G + n0 + thrCol;
        float4 o0, o1;
        o0.x = acc[i][0] + bb[0]; o0.y = acc[i][1] + bb[1];
        o0.z = acc[i][2] + bb[2]; o0.w = acc[i][3] + bb[3];
        o1.x = acc[i][4] + bb[4]; o1.y = acc[i][5] + bb[5];
        o1.z = acc[i][6] + bb[6]; o1.w = acc[i][7] + bb[7];
        reinterpret_cast<float4*>(cp)[0] = o0;
        reinterpret_cast<float4*>(cp)[1] = o1;
    }
}

// ---------------------------------------------------------------------------
// Persistent recurrence kernel: 128 CTAs x 256 threads, one launch per layer.
// CTA owns 4 units (16 gate rows, Wh tile resident in smem for all 1024 steps).
// Thread = (ks, ul, b2): k-half ks, unit-lane ul, batch-lane b2. Each thread
// accumulates partial dots for 2 batches x 4 gates over its k-half; partials
// combined through smem; ks==0 threads do the elementwise update (c in regs).
// Grid-wide sync between steps via monotonic atomic barrier (counter zeroed
// by this layer's GEMM). h staged via __ldcv (L1 not coherent across CTAs).
// ---------------------------------------------------------------------------
#define SMEM_FLOATS (16*512 + 2*64*68 + 2*4*32*4 + 64*16)
#define SMEM_BYTES  (SMEM_FLOATS * 4)

__global__ void __launch_bounds__(NTHR, 1) lstm_persist(
    int layer,
    const float* __restrict__ h0l,
    const float* __restrict__ c0l,
    const float* __restrict__ Wh,      // already offset by D; row stride WROW
    float* __restrict__ dout)
{
    extern __shared__ float sm[];
    float* ws  = sm;                       // [16][512]   gate-rows of Wh (persistent)
    float* hsb = sm + 16 * 512;            // [2][64][68] h tile, per k-half chunk
    float* red = hsb + 2 * 64 * 68;        // [2][4][32][4] k-split partials
    float* xs  = red + 2 * 4 * 32 * 4;     // [64][16]    xg slice for this CTA

    const int tid = threadIdx.x;
    const int ks  = tid >> 7;              // k-half 0/1
    const int r   = tid & 127;
    const int ul  = r >> 5;                // unit lane 0..3 (warp-uniform)
    const int b2  = r & 31;                // batch lane 0..31
    const int u0  = blockIdx.x * 4;
    const int u   = u0 + ul;
    volatile unsigned* bar = &g_bar[layer];

    float* outp = layer ? dout : g_y1;

    // --- Load this CTA's 16 Wh rows (4 units x 4 gates x 512) into smem, once.
#pragma unroll
    for (int p = 0; p < 8; p++) {
        const int fidx = tid + p * NTHR;   // float4 index 0..2047
        const int row  = fidx >> 7;        // 0..15  (= gate*4 + uu)
        const int c4   = fidx & 127;
        const int g    = row >> 2, uu = row & 3;
        const float4 v = *reinterpret_cast<const float4*>(
            Wh + (size_t)(g * H + u0 + uu) * WROW + c4 * 4);
        *reinterpret_cast<float4*>(&ws[row * 512 + c4 * 4]) = v;
    }

    // --- Cell state lives in registers of the ks==0 owner thread.
    float c_loc0 = 0.f, c_loc1 = 0.f;
    if (ks == 0) {
        c_loc0 = c0l[b2 * H + u];
        c_loc1 = c0l[(b2 + 32) * H + u];
    }
    __syncthreads();

    float* hsj = hsb + ks * (64 * 68);
    const int bX = tid >> 2, gX = tid & 3;   // xg prefetch mapping

    for (int t = 0; t < S; t++) {
        const float* hin = (t == 0) ? h0l : g_h[(t + 1) & 1];
        float* hout = g_h[t & 1];
        const float* xg = g_xg + (size_t)t * B * G;

        // Prefetch xg slice for this CTA: 64 b x 16 cols (4 gates x 4 units).
        {
            const float4 xv = *reinterpret_cast<const float4*>(
                xg + (size_t)bX * G + gX * 512 + u0);
            *reinterpret_cast<float4*>(&xs[bX * 16 + gX * 4]) = xv;
        }

        float a00=0.f,a01=0.f,a02=0.f,a03=0.f;   // batch b2
        float a10=0.f,a11=0.f,a12=0.f,a13=0.f;   // batch b2+32

#pragma unroll 1
        for (int ch = 0; ch < 4; ch++) {
            // Stage h chunk: both k-halves' 64-col slices for all 64 batches.
#pragma unroll
            for (int p = 0; p < 8; p++) {
                const int fidx = tid + p * NTHR;      // float4 index 0..2047
                const int j    = fidx >> 10;
                const int rem  = fidx & 1023;
                const int row  = rem >> 4;
                const int c4   = rem & 15;
                const float4 v = __ldcv(reinterpret_cast<const float4*>(
                    hin + (size_t)row * H + j * 256 + ch * 64 + c4 * 4));
                *reinterpret_cast<float4*>(&hsb[(j * 64 + row) * 68 + c4 * 4]) = v;
            }
            __syncthreads();

            const int colbase = ks * 256 + ch * 64;
            const float* wp0 = ws + (0 * 4 + ul) * 512 + colbase;
            const float* wp1 = ws + (1 * 4 + ul) * 512 + colbase;
            const float* wp2 = ws + (2 * 4 + ul) * 512 + colbase;
            const float* wp3 = ws + (3 * 4 + ul) * 512 + colbase;
            const float* h0p = hsj + b2 * 68;
            const float* h1p = hsj + (b2 + 32) * 68;

#pragma unroll
            for (int kk = 0; kk < 64; kk += 4) {
                const float4 hv0 = *reinterpret_cast<const float4*>(h0p + kk);
                const float4 hv1 = *reinterpret_cast<const float4*>(h1p + kk);
                const float4 w0 = *reinterpret_cast<const float4*>(wp0 + kk);  // broadcast
                const float4 w1 = *reinterpret_cast<const float4*>(wp1 + kk);
                const float4 w2 = *reinterpret_cast<const float4*>(wp2 + kk);
                const float4 w3 = *reinterpret_cast<const float4*>(wp3 + kk);
                a00 = fmaf(hv0.x,w0.x,a00); a00 = fmaf(hv0.y,w0.y,a00);
                a00 = fmaf(hv0.z,w0.z,a00); a00 = fmaf(hv0.w,w0.w,a00);
                a01 = fmaf(hv0.x,w1.x,a01); a01 = fmaf(hv0.y,w1.y,a01);
                a01 = fmaf(hv0.z,w1.z,a01); a01 = fmaf(hv0.w,w1.w,a01);
                a02 = fmaf(hv0.x,w2.x,a02); a02 = fmaf(hv0.y,w2.y,a02);
                a02 = fmaf(hv0.z,w2.z,a02); a02 = fmaf(hv0.w,w2.w,a02);
                a03 = fmaf(hv0.x,w3.x,a03); a03 = fmaf(hv0.y,w3.y,a03);
                a03 = fmaf(hv0.z,w3.z,a03); a03 = fmaf(hv0.w,w3.w,a03);
                a10 = fmaf(hv1.x,w0.x,a10); a10 = fmaf(hv1.y,w0.y,a10);
                a10 = fmaf(hv1.z,w0.z,a10); a10 = fmaf(hv1.w,w0.w,a10);
                a11 = fmaf(hv1.x,w1.x,a11); a11 = fmaf(hv1.y,w1.y,a11);
                a11 = fmaf(hv1.z,w1.z,a11); a11 = fmaf(hv1.w,w1.w,a11);
                a12 = fmaf(hv1.x,w2.x,a12); a12 = fmaf(hv1.y,w2.y,a12);
                a12 = fmaf(hv1.z,w2.z,a12); a12 = fmaf(hv1.w,w2.w,a12);
                a13 = fmaf(hv1.x,w3.x,a13); a13 = fmaf(hv1.y,w3.y,a13);
                a13 = fmaf(hv1.z,w3.z,a13); a13 = fmaf(hv1.w,w3.w,a13);
            }
            __syncthreads();   // protect hs restage
        }

        // k-split reduction through smem
        if (ks == 1) {
            *reinterpret_cast<float4*>(&red[((0 * 4 + ul) * 32 + b2) * 4]) =
                make_float4(a00, a01, a02, a03);
            *reinterpret_cast<float4*>(&red[((1 * 4 + ul) * 32 + b2) * 4]) =
                make_float4(a10, a11, a12, a13);
        }
        __syncthreads();

        if (ks == 0) {
            const float4 r0 = *reinterpret_cast<const float4*>(&red[((0 * 4 + ul) * 32 + b2) * 4]);
            const float4 r1 = *reinterpret_cast<const float4*>(&red[((1 * 4 + ul) * 32 + b2) * 4]);

            // batch b = b2
            {
                const float gi = a00 + r0.x + xs[b2 * 16 + 0 * 4 + ul];
                const float gf = a01 + r0.y + xs[b2 * 16 + 1 * 4 + ul];
                const float go = a02 + r0.z + xs[b2 * 16 + 2 * 4 + ul];
                const float gg = a03 + r0.w + xs[b2 * 16 + 3 * 4 + ul];
                const float i_ = __fdividef(1.f, 1.f + __expf(-gi));
                const float f_ = __fdividef(1.f, 1.f + __expf(-gf));
                const float o_ = __fdividef(1.f, 1.f + __expf(-go));
                const float g_ = tanhf(gg);
                c_loc0 = f_ * c_loc0 + i_ * g_;
                const float hnew = o_ * tanhf(c_loc0);
                hout[b2 * H + u] = hnew;
                outp[(size_t)b2 * S * H + (size_t)t * H + u] = hnew;
                if (t == S - 1) {
                    const size_t BSH = (size_t)B * S * H, BH = (size_t)B * H;
                    dout[BSH + (size_t)layer * BH + b2 * H + u] = hnew;
                    dout[BSH + 2 * BH + (size_t)layer * BH + b2 * H + u] = c_loc0;
                }
            }
            // batch b = b2 + 32
            {
                const int b = b2 + 32;
                const float gi = a10 + r1.x + xs[b * 16 + 0 * 4 + ul];
                const float gf = a11 + r1.y + xs[b * 16 + 1 * 4 + ul];
                const float go = a12 + r1.z + xs[b * 16 + 2 * 4 + ul];
                const float gg = a13 + r1.w + xs[b * 16 + 3 * 4 + ul];
                const float i_ = __fdividef(1.f, 1.f + __expf(-gi));
                const float f_ = __fdividef(1.f, 1.f + __expf(-gf));
                const float o_ = __fdividef(1.f, 1.f + __expf(-go));
                const float g_ = tanhf(gg);
                c_loc1 = f_ * c_loc1 + i_ * g_;
                const float hnew = o_ * tanhf(c_loc1);
                hout[b * H + u] = hnew;
                outp[(size_t)b * S * H + (size_t)t * H + u] = hnew;
                if (t == S - 1) {
                    const size_t BSH = (size_t)B * S * H, BH = (size_t)B * H;
                    dout[BSH + (size_t)layer * BH + b * H + u] = hnew;
                    dout[BSH + 2 * BH + (size_t)layer * BH + b * H + u] = c_loc1;
                }
            }
        }

        // Grid-wide barrier between steps (skip after last step).
        if (t != S - 1) {
            __threadfence();            // make this thread's h writes GPU-visible
            __syncthreads();
            if (tid == 0) {
                atomicAdd((unsigned*)bar, 1u);
                const unsigned tgt = (unsigned)(t + 1) * NCTA;
                while (*bar < tgt) { }  // monotonic counter: no reset race
            }
            __syncthreads();
        }
    }
}

// ---------------------------------------------------------------------------
// Launch: per layer -> input GEMM (also zeroes barrier), persistent recurrence.
// 4 graph nodes total. No allocs, no syncs, graph-capturable.
// ---------------------------------------------------------------------------
extern "C" void kernel_launch(void* const* d_in, const int* in_sizes, int n_in,
                              void* d_out, int out_size)
{
    const float* x  = (const float*)d_in[0];
    const float* W  = (const float*)d_in[1];
    const float* bb = (const float*)d_in[2];
    const float* h0 = (const float*)d_in[3];
    const float* c0 = (const float*)d_in[4];
    float* out = (float*)d_out;

    cudaFuncSetAttribute(lstm_persist,
                         cudaFuncAttributeMaxDynamicSharedMemorySize, SMEM_BYTES);

    const dim3 ggrid(G / BN, (S * B) / BM);   // 16 x 512

    for (int layer = 0; layer < 2; layer++) {
        const float* Wl = W + (size_t)layer * G * WROW;
        gemm_xw<<<ggrid, 256>>>(x, layer, Wl, bb + layer * G);
        lstm_persist<<<NCTA, NTHR, SMEM_BYTES>>>(
            layer, h0 + layer * B * H, c0 + layer * B * H, Wl + D, out);
    }
}

// round 7
// speedup vs baseline: 1.2811x; 1.2811x over previous
#include <cuda_runtime.h>
#include <cuda_bf16.h>
#include <math.h>
#include <cstdint>

// Problem constants
#define B    64
#define S    1024
#define D    512
#define H    512
#define G    2048      // 4*H
#define WROW 1024      // D+H, row stride of W
#define M_TOT (S*B)    // 65536 GEMM rows, m = t*B + b
#define NCTA 128
#define NTHR 256

// ---------------------------------------------------------------------------
// Scratch (__device__ globals: sanctioned alloc-free workaround)
// ---------------------------------------------------------------------------
__device__ __nv_bfloat16 g_xh [(size_t)M_TOT * 512];   // layer-0 A hi
__device__ __nv_bfloat16 g_xl [(size_t)M_TOT * 512];   // layer-0 A lo
__device__ __nv_bfloat16 g_y1h[(size_t)M_TOT * 512];   // layer-1 A hi (from persist L0)
__device__ __nv_bfloat16 g_y1l[(size_t)M_TOT * 512];   // layer-1 A lo
__device__ __nv_bfloat16 g_wh [2 * (size_t)G * 512];   // Wx hi, [layer][n][k]
__device__ __nv_bfloat16 g_wl [2 * (size_t)G * 512];   // Wx lo
__device__ float g_xg[(size_t)S * B * G];              // input gates (t*B+b, G)
__device__ float g_h[2][B * H];                        // ping-pong hidden state
__device__ unsigned g_bar[2];                          // grid-barrier counters

// ---------------------------------------------------------------------------
// PTX helpers (arch-portable: sm_80+ instructions only; NO tcgen05)
// ---------------------------------------------------------------------------
__device__ __forceinline__ uint32_t smem_u32(const void* p) {
    uint32_t a;
    asm("{ .reg .u64 t; cvta.to.shared.u64 t, %1; cvt.u32.u64 %0, t; }"
        : "=r"(a) : "l"(p));
    return a;
}

#define CPASYNC(sm, gm) \
    asm volatile("cp.async.cg.shared.global [%0], [%1], 16;" :: "r"(sm), "l"(gm))
#define CPCOMMIT() asm volatile("cp.async.commit_group;" ::: "memory")
#define CPWAIT(n)  asm volatile("cp.async.wait_group %0;" :: "n"(n) : "memory")

#define LDSM4(r0, r1, r2, r3, addr) \
    asm volatile("ldmatrix.sync.aligned.m8n8.x4.shared.b16 {%0,%1,%2,%3}, [%4];" \
        : "=r"(r0), "=r"(r1), "=r"(r2), "=r"(r3) : "r"(addr))
#define LDSM2(r0, r1, addr) \
    asm volatile("ldmatrix.sync.aligned.m8n8.x2.shared.b16 {%0,%1}, [%2];" \
        : "=r"(r0), "=r"(r1) : "r"(addr))

#define MMA16816(d, a, b) \
    asm volatile("mma.sync.aligned.m16n8k16.row.col.f32.bf16.bf16.f32 " \
        "{%0,%1,%2,%3},{%4,%5,%6,%7},{%8,%9},{%0,%1,%2,%3};" \
        : "+f"((d)[0]), "+f"((d)[1]), "+f"((d)[2]), "+f"((d)[3]) \
        : "r"((a)[0]), "r"((a)[1]), "r"((a)[2]), "r"((a)[3]), \
          "r"((b)[0]), "r"((b)[1]))

__device__ __forceinline__ void bsplit(float v, __nv_bfloat16& h, __nv_bfloat16& l) {
    h = __float2bfloat16(v);
    l = __float2bfloat16(v - __bfloat162float(h));
}

// ---------------------------------------------------------------------------
// Split kernels: fp32 -> bf16 hi/lo pairs
// ---------------------------------------------------------------------------
__global__ void __launch_bounds__(256) split_x(const float* __restrict__ x)
{
    const size_t i4 = (size_t)blockIdx.x * 256 + threadIdx.x;  // over M_TOT*512/4
    const float4 v = ((const float4*)x)[i4];
    const size_t idx = i4 * 4;                 // (b, t, k) in x layout
    const int k = (int)(idx & 511);
    const int t = (int)((idx >> 9) & 1023);
    const int b = (int)(idx >> 19);
    const size_t o = ((size_t)t * B + b) * 512 + k;   // GEMM A layout (m, k)
    __nv_bfloat16 h0, l0, h1, l1, h2, l2, h3, l3;
    bsplit(v.x, h0, l0); bsplit(v.y, h1, l1);
    bsplit(v.z, h2, l2); bsplit(v.w, h3, l3);
    __nv_bfloat162 a, bb2;
    a.x = h0; a.y = h1; bb2.x = h2; bb2.y = h3;
    *(__nv_bfloat162*)(g_xh + o)     = a;
    *(__nv_bfloat162*)(g_xh + o + 2) = bb2;
    a.x = l0; a.y = l1; bb2.x = l2; bb2.y = l3;
    *(__nv_bfloat162*)(g_xl + o)     = a;
    *(__nv_bfloat162*)(g_xl + o + 2) = bb2;
}

__global__ void __launch_bounds__(256) split_w(const float* __restrict__ W)
{
    const size_t i4 = (size_t)blockIdx.x * 256 + threadIdx.x;  // over 2*G*512/4
    const size_t idx = i4 * 4;
    const int k = (int)(idx & 511);
    const int n = (int)((idx >> 9) & 2047);
    const int layer = (int)(idx >> 20);
    const float4 v = *(const float4*)(W + ((size_t)layer * G + n) * WROW + k);
    __nv_bfloat16 h0, l0, h1, l1, h2, l2, h3, l3;
    bsplit(v.x, h0, l0); bsplit(v.y, h1, l1);
    bsplit(v.z, h2, l2); bsplit(v.w, h3, l3);
    __nv_bfloat162 a, bb2;
    a.x = h0; a.y = h1; bb2.x = h2; bb2.y = h3;
    *(__nv_bfloat162*)(g_wh + idx)     = a;
    *(__nv_bfloat162*)(g_wh + idx + 2) = bb2;
    a.x = l0; a.y = l1; bb2.x = l2; bb2.y = l3;
    *(__nv_bfloat162*)(g_wl + idx)     = a;
    *(__nv_bfloat162*)(g_wl + idx + 2) = bb2;
}

// ---------------------------------------------------------------------------
// HMMA bf16-split GEMM: xg[m][n] = sum_k A[m][k]*Wx[n][k] + bias[n]
// D = AhBh + AhBl + AlBh  (fp32 accumulators in registers)
// CTA tile 128x128; 8 warps (2 M x 4 N), warp tile 64x32; mma.m16n8k16.
// K pipeline: 24 chunks (3 terms x 8 chunks of 64), cp.async double buffer.
// SMEM pitch 72 halves (144 B): ldmatrix row addrs cover all 8 16B banks.
// ---------------------------------------------------------------------------
#define APITCH 72
#define ATILEB (128 * APITCH * 2)        // 18432 B per operand tile
#define STAGEB (2 * ATILEB)              // A + B per stage
#define GSMEM  (2 * STAGEB)              // double buffered = 73728 B

__global__ void __launch_bounds__(256) gemm_hmma(
    const float* __restrict__ bias, int layer)
{
    if (blockIdx.x == 0 && blockIdx.y == 0 && threadIdx.x == 0)
        g_bar[layer] = 0u;               // reset grid barrier for this layer

    const __nv_bfloat16* __restrict__ Ah = layer ? g_y1h : g_xh;
    const __nv_bfloat16* __restrict__ Al = layer ? g_y1l : g_xl;
    const __nv_bfloat16* __restrict__ Bh = g_wh + (size_t)layer * G * 512;
    const __nv_bfloat16* __restrict__ Bl = g_wl + (size_t)layer * G * 512;
    const __nv_bfloat16* APs[3] = { Ah, Ah, Al };
    const __nv_bfloat16* BPs[3] = { Bh, Bl, Bh };

    extern __shared__ char dynsm[];
    const uint32_t sbase = smem_u32(dynsm);
    const int tid = threadIdx.x, lane = tid & 31, warp = tid >> 5;
    const int wm = warp & 1, wn = warp >> 1;          // warp grid 2(M) x 4(N)
    const int m0 = blockIdx.y * 128, n0 = blockIdx.x * 128;

    // ldmatrix lane-address bases
    const int sel = lane >> 3, lr = lane & 7;
    const uint32_t aRow  = wm * 64 + (sel & 1) * 8 + lr;      // A x4: 4 mats
    const uint32_t aColB = (sel >> 1) * 8;
    const uint32_t bRow  = wn * 32 + lr;                      // B x2: 2 mats
    const uint32_t bColB = (sel & 1) * 8;

    float d[4][4][4];
#pragma unroll
    for (int i = 0; i < 4; i++)
#pragma unroll
        for (int j = 0; j < 4; j++)
#pragma unroll
            for (int q = 0; q < 4; q++) d[i][j][q] = 0.0f;

    // issue one chunk's cp.async loads into buffer `buf`
    auto issue = [&](int c, int buf) {
        const int term = c >> 3, kg = (c & 7) * 64;
        const __nv_bfloat16* Ap = APs[term];
        const __nv_bfloat16* Bp = BPs[term];
        const uint32_t sA = sbase + buf * STAGEB;
        const uint32_t sB = sA + ATILEB;
#pragma unroll
        for (int p = 0; p < 4; p++) {
            const int f = tid + p * 256;           // 0..1023 16B segs per tile
            const int row = f >> 3, seg = f & 7;
            const uint32_t so = (uint32_t)(row * APITCH + seg * 8) * 2;
            CPASYNC(sA + so, Ap + (size_t)(m0 + row) * 512 + kg + seg * 8);
            CPASYNC(sB + so, Bp + (size_t)(n0 + row) * 512 + kg + seg * 8);
        }
        CPCOMMIT();
    };

    issue(0, 0);
    for (int c = 0; c < 24; c++) {
        const int buf = c & 1;
        if (c + 1 < 24) { issue(c + 1, buf ^ 1); CPWAIT(1); }
        else            { CPWAIT(0); }
        __syncthreads();

        const uint32_t sA = sbase + buf * STAGEB;
        const uint32_t sB = sA + ATILEB;
        const uint32_t aBase = sA + (aRow * APITCH + aColB) * 2;
        const uint32_t bBase = sB + (bRow * APITCH + bColB) * 2;

#pragma unroll
        for (int ks = 0; ks < 4; ks++) {           // 4 k16 steps per 64-chunk
            uint32_t a[4][4], b[4][2];
#pragma unroll
            for (int i = 0; i < 4; i++)
                LDSM4(a[i][0], a[i][1], a[i][2], a[i][3],
                      aBase + (uint32_t)(i * 16 * APITCH + ks * 16) * 2);
#pragma unroll
            for (int j = 0; j < 4; j++)
                LDSM2(b[j][0], b[j][1],
                      bBase + (uint32_t)(j * 8 * APITCH + ks * 16) * 2);
#pragma unroll
            for (int i = 0; i < 4; i++)
#pragma unroll
                for (int j = 0; j < 4; j++)
                    MMA16816(d[i][j], a[i], b[j]);
        }
        __syncthreads();     // all warps done with buf before it is re-filled
    }

    // Epilogue: accumulators + bias -> g_xg
    const int gq = lane >> 2, tq = lane & 3;
#pragma unroll
    for (int i = 0; i < 4; i++) {
#pragma unroll
        for (int j = 0; j < 4; j++) {
            const int col = n0 + wn * 32 + j * 8 + tq * 2;
            const int row0 = m0 + wm * 64 + i * 16 + gq;
            const float b0 = bias[col], b1 = bias[col + 1];
            float2 v0, v1;
            v0.x = d[i][j][0] + b0; v0.y = d[i][j][1] + b1;
            v1.x = d[i][j][2] + b0; v1.y = d[i][j][3] + b1;
            *(float2*)(g_xg + (size_t)row0 * G + col) = v0;
            *(float2*)(g_xg + (size_t)(row0 + 8) * G + col) = v1;
        }
    }
}

// ---------------------------------------------------------------------------
// Persistent recurrence: 128 CTAs x 256 threads, one launch per layer.
// CTA owns 4 units (16 gate rows of Wh resident in smem). Per step: stage full
// h (64x512, pitch 516) ONCE, then one uninterrupted FFMA loop (k-split 2).
// Layer 0 writes y1 as bf16 hi/lo in GEMM layout; layer 1 writes fp32 d_out.
// ---------------------------------------------------------------------------
#define P_SMEM_FLOATS (16 * 512 + 64 * 516 + 64 * 16 + 1024)
#define P_SMEM_BYTES  (P_SMEM_FLOATS * 4)          // 173056

__global__ void __launch_bounds__(NTHR, 1) lstm_persist(
    int layer,
    const float* __restrict__ h0l,
    const float* __restrict__ c0l,
    const float* __restrict__ Wh,      // already offset by D; row stride WROW
    float* __restrict__ dout)
{
    extern __shared__ char dynsm[];
    float* sm  = (float*)dynsm;
    float* ws  = sm;                    // [16][512]  Wh gate rows (persistent)
    float* hs  = sm + 16 * 512;         // [64][516]  full h tile per step
    float* xs  = hs + 64 * 516;         // [64][16]   xg slice
    float* red = xs + 64 * 16;          // [2][4][32][4] k-split partials

    const int tid = threadIdx.x;
    const int ks  = tid >> 7;           // k-half 0/1
    const int r   = tid & 127;
    const int ul  = r >> 5;             // unit lane (warp-uniform)
    const int b2  = r & 31;             // batch lane
    const int u0  = blockIdx.x * 4;
    const int u   = u0 + ul;
    volatile unsigned* bar = &g_bar[layer];

    // Wh rows into smem once
#pragma unroll
    for (int p = 0; p < 8; p++) {
        const int fidx = tid + p * NTHR;
        const int row = fidx >> 7, c4 = fidx & 127;
        const int g = row >> 2, uu = row & 3;
        const float4 v = *(const float4*)(Wh + (size_t)(g * H + u0 + uu) * WROW + c4 * 4);
        *(float4*)(&ws[row * 512 + c4 * 4]) = v;
    }
    float cv0 = 0.f, cv1 = 0.f;
    if (ks == 0) {
        cv0 = c0l[b2 * H + u];
        cv1 = c0l[(b2 + 32) * H + u];
    }
    __syncthreads();

    const int bX = tid >> 2, gX = tid & 3;

    for (int t = 0; t < S; t++) {
        const float* hin = (t == 0) ? h0l : g_h[(t + 1) & 1];
        float* hout = g_h[t & 1];
        const float* xg = g_xg + (size_t)t * B * G;

        // xg prefetch (overlaps stage + compute; consumed after reduction sync)
        {
            const float4 xv = *(const float4*)(xg + (size_t)bX * G + gX * 512 + u0);
            *(float4*)(&xs[bX * 16 + gX * 4]) = xv;
        }
        // stage full h: 8192 float4 / 256 threads, L1-bypass (cross-CTA coherence)
#pragma unroll
        for (int p = 0; p < 32; p++) {
            const int fidx = tid + p * NTHR;
            const int row = fidx >> 7, c4 = fidx & 127;
            const float4 v = __ldcv((const float4*)(hin + (size_t)row * H + c4 * 4));
            *(float4*)(&hs[row * 516 + c4 * 4]) = v;
        }
        __syncthreads();

        float a00 = 0.f, a01 = 0.f, a02 = 0.f, a03 = 0.f;
        float a10 = 0.f, a11 = 0.f, a12 = 0.f, a13 = 0.f;
        const float* wp0 = ws + (0 * 4 + ul) * 512 + ks * 256;
        const float* wp1 = ws + (1 * 4 + ul) * 512 + ks * 256;
        const float* wp2 = ws + (2 * 4 + ul) * 512 + ks * 256;
        const float* wp3 = ws + (3 * 4 + ul) * 512 + ks * 256;
        const float* hp0 = hs + b2 * 516 + ks * 256;
        const float* hp1 = hs + (b2 + 32) * 516 + ks * 256;

#pragma unroll 8
        for (int kk = 0; kk < 256; kk += 4) {
            const float4 hv0 = *(const float4*)(hp0 + kk);
            const float4 hv1 = *(const float4*)(hp1 + kk);
            const float4 w0 = *(const float4*)(wp0 + kk);   // broadcast
            const float4 w1 = *(const float4*)(wp1 + kk);
            const float4 w2 = *(const float4*)(wp2 + kk);
            const float4 w3 = *(const float4*)(wp3 + kk);
            a00 = fmaf(hv0.x,w0.x,a00); a00 = fmaf(hv0.y,w0.y,a00);
            a00 = fmaf(hv0.z,w0.z,a00); a00 = fmaf(hv0.w,w0.w,a00);
            a01 = fmaf(hv0.x,w1.x,a01); a01 = fmaf(hv0.y,w1.y,a01);
            a01 = fmaf(hv0.z,w1.z,a01); a01 = fmaf(hv0.w,w1.w,a01);
            a02 = fmaf(hv0.x,w2.x,a02); a02 = fmaf(hv0.y,w2.y,a02);
            a02 = fmaf(hv0.z,w2.z,a02); a02 = fmaf(hv0.w,w2.w,a02);
            a03 = fmaf(hv0.x,w3.x,a03); a03 = fmaf(hv0.y,w3.y,a03);
            a03 = fmaf(hv0.z,w3.z,a03); a03 = fmaf(hv0.w,w3.w,a03);
            a10 = fmaf(hv1.x,w0.x,a10); a10 = fmaf(hv1.y,w0.y,a10);
            a10 = fmaf(hv1.z,w0.z,a10); a10 = fmaf(hv1.w,w0.w,a10);
            a11 = fmaf(hv1.x,w1.x,a11); a11 = fmaf(hv1.y,w1.y,a11);
            a11 = fmaf(hv1.z,w1.z,a11); a11 = fmaf(hv1.w,w1.w,a11);
            a12 = fmaf(hv1.x,w2.x,a12); a12 = fmaf(hv1.y,w2.y,a12);
            a12 = fmaf(hv1.z,w2.z,a12); a12 = fmaf(hv1.w,w2.w,a12);
            a13 = fmaf(hv1.x,w3.x,a13); a13 = fmaf(hv1.y,w3.y,a13);
            a13 = fmaf(hv1.z,w3.z,a13); a13 = fmaf(hv1.w,w3.w,a13);
        }

        if (ks == 1) {
            *(float4*)(&red[((0 * 4 + ul) * 32 + b2) * 4]) = make_float4(a00, a01, a02, a03);
            *(float4*)(&red[((1 * 4 + ul) * 32 + b2) * 4]) = make_float4(a10, a11, a12, a13);
        }
        __syncthreads();

        if (ks == 0) {
            const float4 r0 = *(const float4*)(&red[((0 * 4 + ul) * 32 + b2) * 4]);
            const float4 r1 = *(const float4*)(&red[((1 * 4 + ul) * 32 + b2) * 4]);
#pragma unroll
            for (int half = 0; half < 2; half++) {
                const int b = b2 + half * 32;
                const float p0 = half ? a10 : a00, p1 = half ? a11 : a01;
                const float p2 = half ? a12 : a02, p3 = half ? a13 : a03;
                const float4 rr = half ? r1 : r0;
                const float gi = p0 + rr.x + xs[b * 16 + 0 * 4 + ul];
                const float gf = p1 + rr.y + xs[b * 16 + 1 * 4 + ul];
                const float go = p2 + rr.z + xs[b * 16 + 2 * 4 + ul];
                const float gg = p3 + rr.w + xs[b * 16 + 3 * 4 + ul];
                const float i_ = __fdividef(1.f, 1.f + __expf(-gi));
                const float f_ = __fdividef(1.f, 1.f + __expf(-gf));
                const float o_ = __fdividef(1.f, 1.f + __expf(-go));
                const float gv = tanhf(gg);
                float& cl = half ? cv1 : cv0;
                cl = f_ * cl + i_ * gv;
                const float hnew = o_ * tanhf(cl);
                hout[b * H + u] = hnew;
                if (layer == 0) {
                    __nv_bfloat16 hh, hl;
                    bsplit(hnew, hh, hl);
                    const size_t o = ((size_t)t * B + b) * 512 + u;
                    g_y1h[o] = hh;
                    g_y1l[o] = hl;
                } else {
                    dout[(size_t)b * S * H + (size_t)t * H + u] = hnew;
                }
                if (t == S - 1) {
                    const size_t BSH = (size_t)B * S * H, BH = (size_t)B * H;
                    dout[BSH + (size_t)layer * BH + b * H + u] = hnew;
                    dout[BSH + 2 * BH + (size_t)layer * BH + b * H + u] = cl;
                }
            }
        }

        if (t != S - 1) {
            __threadfence();
            __syncthreads();
            if (tid == 0) {
                atomicAdd((unsigned*)bar, 1u);
                const unsigned tgt = (unsigned)(t + 1) * NCTA;
                while (*bar < tgt) { }     // monotonic: no reset race
            }
            __syncthreads();
        }
    }
}

// ---------------------------------------------------------------------------
// Launch: split_x, split_w, then per layer: HMMA GEMM + persistent LSTM.
// 6 graph nodes. No allocs, no syncs, graph-capturable.
// ---------------------------------------------------------------------------
extern "C" void kernel_launch(void* const* d_in, const int* in_sizes, int n_in,
                              void* d_out, int out_size)
{
    const float* x  = (const float*)d_in[0];
    const float* W  = (const float*)d_in[1];
    const float* bb = (const float*)d_in[2];
    const float* h0 = (const float*)d_in[3];
    const float* c0 = (const float*)d_in[4];
    float* out = (float*)d_out;

    cudaFuncSetAttribute(gemm_hmma, cudaFuncAttributeMaxDynamicSharedMemorySize, GSMEM);
    cudaFuncSetAttribute(lstm_persist, cudaFuncAttributeMaxDynamicSharedMemorySize, P_SMEM_BYTES);

    split_x<<<(M_TOT * 512 / 4) / 256, 256>>>(x);
    split_w<<<(2 * G * 512 / 4) / 256, 256>>>(W);

    for (int layer = 0; layer < 2; layer++) {
        gemm_hmma<<<dim3(16, 512), 256, GSMEM>>>(bb + layer * G, layer);
        lstm_persist<<<NCTA, NTHR, P_SMEM_BYTES>>>(
            layer, h0 + layer * B * H, c0 + layer * B * H,
            W + (size_t)layer * G * WROW + D, out);
    }
}

// round 9
// speedup vs baseline: 1.7284x; 1.3492x over previous
#include <cuda_runtime.h>
#include <cuda_bf16.h>
#include <math.h>
#include <cstdint>

// Problem constants
#define B    64
#define S    1024
#define D    512
#define H    512
#define G    2048      // 4*H
#define WROW 1024      // D+H, row stride of W
#define M_TOT (S*B)    // 65536 GEMM rows, m = t*B + b
#define NCTA 128
#define NTHR 256

// ---------------------------------------------------------------------------
// Scratch (__device__ globals: sanctioned alloc-free workaround)
// ---------------------------------------------------------------------------
__device__ __nv_bfloat16 g_xh [(size_t)M_TOT * 512];     // layer-0 A hi
__device__ __nv_bfloat16 g_xl [(size_t)M_TOT * 512];     // layer-0 A lo
__device__ __nv_bfloat16 g_y1h[(size_t)M_TOT * 512];     // layer-1 A hi
__device__ __nv_bfloat16 g_y1l[(size_t)M_TOT * 512];     // layer-1 A lo
__device__ __nv_bfloat16 g_wh [2 * (size_t)G * WROW];    // W hi, [layer][n][WROW]
__device__ __nv_bfloat16 g_wl [2 * (size_t)G * WROW];    // W lo
__device__ float g_xg[(size_t)S * B * G];                // input gates (t*B+b, G)
__device__ __nv_bfloat16 g_hbf[2][2][B * H];             // ping-pong h, [buf][hi/lo]
__device__ unsigned g_bar[2];                            // grid-barrier counters

// ---------------------------------------------------------------------------
// PTX helpers (arch-portable: sm_80+ only)
// ---------------------------------------------------------------------------
__device__ __forceinline__ uint32_t smem_u32(const void* p) {
    uint32_t a;
    asm("{ .reg .u64 t; cvta.to.shared.u64 t, %1; cvt.u32.u64 %0, t; }"
        : "=r"(a) : "l"(p));
    return a;
}

#define CPASYNC(sm, gm) \
    asm volatile("cp.async.cg.shared.global [%0], [%1], 16;" :: "r"(sm), "l"(gm))
#define CPCOMMIT() asm volatile("cp.async.commit_group;" ::: "memory")
#define CPWAIT(n)  asm volatile("cp.async.wait_group %0;" :: "n"(n) : "memory")

#define LDSM4(r0, r1, r2, r3, addr) \
    asm volatile("ldmatrix.sync.aligned.m8n8.x4.shared.b16 {%0,%1,%2,%3}, [%4];" \
        : "=r"(r0), "=r"(r1), "=r"(r2), "=r"(r3) : "r"(addr))
#define LDSM2(r0, r1, addr) \
    asm volatile("ldmatrix.sync.aligned.m8n8.x2.shared.b16 {%0,%1}, [%2];" \
        : "=r"(r0), "=r"(r1) : "r"(addr))

#define MMA16816(d, a, b) \
    asm volatile("mma.sync.aligned.m16n8k16.row.col.f32.bf16.bf16.f32 " \
        "{%0,%1,%2,%3},{%4,%5,%6,%7},{%8,%9},{%0,%1,%2,%3};" \
        : "+f"((d)[0]), "+f"((d)[1]), "+f"((d)[2]), "+f"((d)[3]) \
        : "r"((a)[0]), "r"((a)[1]), "r"((a)[2]), "r"((a)[3]), \
          "r"((b)[0]), "r"((b)[1]))

__device__ __forceinline__ void bsplit(float v, __nv_bfloat16& h, __nv_bfloat16& l) {
    h = __float2bfloat16(v);
    l = __float2bfloat16(v - __bfloat162float(h));
}

// ---------------------------------------------------------------------------
// Split kernels: fp32 -> bf16 hi/lo
// ---------------------------------------------------------------------------
__global__ void __launch_bounds__(256) split_x(const float* __restrict__ x)
{
    const size_t i4 = (size_t)blockIdx.x * 256 + threadIdx.x;  // over M_TOT*512/4
    const float4 v = ((const float4*)x)[i4];
    const size_t idx = i4 * 4;                 // (b, t, k) in x layout
    const int k = (int)(idx & 511);
    const int t = (int)((idx >> 9) & 1023);
    const int b = (int)(idx >> 19);
    const size_t o = ((size_t)t * B + b) * 512 + k;   // GEMM A layout (m, k)
    __nv_bfloat16 h0, l0, h1, l1, h2, l2, h3, l3;
    bsplit(v.x, h0, l0); bsplit(v.y, h1, l1);
    bsplit(v.z, h2, l2); bsplit(v.w, h3, l3);
    __nv_bfloat162 a, bb2;
    a.x = h0; a.y = h1; bb2.x = h2; bb2.y = h3;
    *(__nv_bfloat162*)(g_xh + o)     = a;
    *(__nv_bfloat162*)(g_xh + o + 2) = bb2;
    a.x = l0; a.y = l1; bb2.x = l2; bb2.y = l3;
    *(__nv_bfloat162*)(g_xl + o)     = a;
    *(__nv_bfloat162*)(g_xl + o + 2) = bb2;
}

// Full-W split: source layout [layer][n][WROW] is copied linearly.
__global__ void __launch_bounds__(256) split_w(const float* __restrict__ W)
{
    const size_t i4 = (size_t)blockIdx.x * 256 + threadIdx.x;  // over 2*G*WROW/4
    const float4 v = ((const float4*)W)[i4];
    const size_t idx = i4 * 4;
    __nv_bfloat16 h0, l0, h1, l1, h2, l2, h3, l3;
    bsplit(v.x, h0, l0); bsplit(v.y, h1, l1);
    bsplit(v.z, h2, l2); bsplit(v.w, h3, l3);
    __nv_bfloat162 a, bb2;
    a.x = h0; a.y = h1; bb2.x = h2; bb2.y = h3;
    *(__nv_bfloat162*)(g_wh + idx)     = a;
    *(__nv_bfloat162*)(g_wh + idx + 2) = bb2;
    a.x = l0; a.y = l1; bb2.x = l2; bb2.y = l3;
    *(__nv_bfloat162*)(g_wl + idx)     = a;
    *(__nv_bfloat162*)(g_wl + idx + 2) = bb2;
}

// Convert h0 (fp32) into the bf16 ping-pong buffer read at t=0 (index 1).
__global__ void __launch_bounds__(256) init_h(const float* __restrict__ h0l)
{
    const int i = blockIdx.x * 256 + threadIdx.x;   // 0..B*H-1
    __nv_bfloat16 hh, hl;
    bsplit(h0l[i], hh, hl);
    g_hbf[1][0][i] = hh;
    g_hbf[1][1][i] = hl;
}

// ---------------------------------------------------------------------------
// HMMA bf16-split GEMM: xg[m][n] = sum_k A[m][k]*Wx[n][k] + bias[n]
// D = AhBh + AhBl + AlBh  (fp32 accumulators in registers)
// CTA tile 128x128; 8 warps (2 M x 4 N), warp tile 64x32; mma.m16n8k16.
// K pipeline: 24 chunks (3 terms x 8 chunks of 64), cp.async double buffer.
// ---------------------------------------------------------------------------
#define APITCH 72
#define ATILEB (128 * APITCH * 2)        // 18432 B per operand tile
#define STAGEB (2 * ATILEB)              // A + B per stage
#define GSMEM  (2 * STAGEB)              // double buffered = 73728 B

__global__ void __launch_bounds__(256) gemm_hmma(
    const float* __restrict__ bias, int layer)
{
    if (blockIdx.x == 0 && blockIdx.y == 0 && threadIdx.x == 0)
        g_bar[layer] = 0u;               // reset grid barrier for this layer

    const __nv_bfloat16* __restrict__ Ah = layer ? g_y1h : g_xh;
    const __nv_bfloat16* __restrict__ Al = layer ? g_y1l : g_xl;
    const __nv_bfloat16* __restrict__ Bh = g_wh + (size_t)layer * G * WROW;
    const __nv_bfloat16* __restrict__ Bl = g_wl + (size_t)layer * G * WROW;
    const __nv_bfloat16* APs[3] = { Ah, Ah, Al };
    const __nv_bfloat16* BPs[3] = { Bh, Bl, Bh };

    extern __shared__ char dynsm[];
    const uint32_t sbase = smem_u32(dynsm);
    const int tid = threadIdx.x, lane = tid & 31, warp = tid >> 5;
    const int wm = warp & 1, wn = warp >> 1;          // warp grid 2(M) x 4(N)
    const int m0 = blockIdx.y * 128, n0 = blockIdx.x * 128;

    const int sel = lane >> 3, lr = lane & 7;
    const uint32_t aRow  = wm * 64 + (sel & 1) * 8 + lr;
    const uint32_t aColB = (sel >> 1) * 8;
    const uint32_t bRow  = wn * 32 + lr;
    const uint32_t bColB = (sel & 1) * 8;

    float d[4][4][4];
#pragma unroll
    for (int i = 0; i < 4; i++)
#pragma unroll
        for (int j = 0; j < 4; j++)
#pragma unroll
            for (int q = 0; q < 4; q++) d[i][j][q] = 0.0f;

    auto issue = [&](int c, int buf) {
        const int term = c >> 3, kg = (c & 7) * 64;
        const __nv_bfloat16* Ap = APs[term];
        const __nv_bfloat16* Bp = BPs[term];
        const uint32_t sA = sbase + buf * STAGEB;
        const uint32_t sB = sA + ATILEB;
#pragma unroll
        for (int p = 0; p < 4; p++) {
            const int f = tid + p * 256;
            const int row = f >> 3, seg = f & 7;
            const uint32_t so = (uint32_t)(row * APITCH + seg * 8) * 2;
            CPASYNC(sA + so, Ap + (size_t)(m0 + row) * 512 + kg + seg * 8);
            CPASYNC(sB + so, Bp + (size_t)(n0 + row) * WROW + kg + seg * 8);
        }
        CPCOMMIT();
    };

    issue(0, 0);
    for (int c = 0; c < 24; c++) {
        const int buf = c & 1;
        if (c + 1 < 24) { issue(c + 1, buf ^ 1); CPWAIT(1); }
        else            { CPWAIT(0); }
        __syncthreads();

        const uint32_t sA = sbase + buf * STAGEB;
        const uint32_t sB = sA + ATILEB;
        const uint32_t aBase = sA + (aRow * APITCH + aColB) * 2;
        const uint32_t bBase = sB + (bRow * APITCH + bColB) * 2;

#pragma unroll
        for (int ks = 0; ks < 4; ks++) {
            uint32_t a[4][4], b[4][2];
#pragma unroll
            for (int i = 0; i < 4; i++)
                LDSM4(a[i][0], a[i][1], a[i][2], a[i][3],
                      aBase + (uint32_t)(i * 16 * APITCH + ks * 16) * 2);
#pragma unroll
            for (int j = 0; j < 4; j++)
                LDSM2(b[j][0], b[j][1],
                      bBase + (uint32_t)(j * 8 * APITCH + ks * 16) * 2);
#pragma unroll
            for (int i = 0; i < 4; i++)
#pragma unroll
                for (int j = 0; j < 4; j++)
                    MMA16816(d[i][j], a[i], b[j]);
        }
        __syncthreads();
    }

    const int gq = lane >> 2, tq = lane & 3;
#pragma unroll
    for (int i = 0; i < 4; i++) {
#pragma unroll
        for (int j = 0; j < 4; j++) {
            const int col = n0 + wn * 32 + j * 8 + tq * 2;
            const int row0 = m0 + wm * 64 + i * 16 + gq;
            const float b0 = bias[col], b1 = bias[col + 1];
            float2 v0, v1;
            v0.x = d[i][j][0] + b0; v0.y = d[i][j][1] + b1;
            v1.x = d[i][j][2] + b0; v1.y = d[i][j][3] + b1;
            *(float2*)(g_xg + (size_t)row0 * G + col) = v0;
            *(float2*)(g_xg + (size_t)(row0 + 8) * G + col) = v1;
        }
    }
}

// ---------------------------------------------------------------------------
// Persistent HMMA recurrence: 128 CTAs x 256 thr (8 warps = 4 M-tiles x 2
// K-halves). CTA owns 16 gate-cols (4 units x 4 gates), Wh bf16 hi/lo
// resident in smem. Per step: cp.async-stage h (bf16 hi/lo) -> 16 k-steps of
// 6 mma per warp (AhBh + AhBl + AlBh) -> k-reduce + gate exchange via smem
// -> elementwise update. h published as bf16 hi/lo for the next step.
// ---------------------------------------------------------------------------
#define HPITCH 520                       // halves per row: 1040 B, 16 B phase-clean
#define HS_H   0
#define HS_L   (HS_H + 64 * HPITCH * 2)      // 66560
#define WS_H   (HS_L + 64 * HPITCH * 2)      // 133120
#define WS_L   (WS_H + 16 * HPITCH * 2)      // 149760
#define XS_OFF (WS_L + 16 * HPITCH * 2)      // 166400, [64][16] fp32
#define GR_OFF (XS_OFF + 64 * 16 * 4)        // 170496, [64][18] fp32
#define P2_SMEM (GR_OFF + 64 * 18 * 4)       // 175104 B

__global__ void __launch_bounds__(NTHR, 1) lstm_persist(
    int layer,
    const float* __restrict__ c0l,
    float* __restrict__ dout)
{
    extern __shared__ char dynsm[];
    const uint32_t sb = smem_u32(dynsm);
    const int tid = threadIdx.x, lane = tid & 31, warp = tid >> 5;
    const int wm = warp & 3;            // m-tile: batches [wm*16, wm*16+16)
    const int wk = warp >> 2;           // k-half: k in [wk*256, wk*256+256)
    const int u0 = blockIdx.x * 4;
    volatile unsigned* bar = &g_bar[layer];

    // --- Stage Wh rows (16 x 512, hi/lo) into smem once. Row n = gate*4+uu.
    {
        const __nv_bfloat16* whH = g_wh + (size_t)layer * G * WROW;
        const __nv_bfloat16* whL = g_wl + (size_t)layer * G * WROW;
#pragma unroll
        for (int p = 0; p < 4; p++) {
            const int f = tid + p * NTHR;          // 1024 segs per tile
            const int row = f >> 6, seg = f & 63;
            const int g = row >> 2, uu = row & 3;
            const size_t src = (size_t)(g * 512 + u0 + uu) * WROW + 512 + seg * 8;
            const uint32_t dst = (uint32_t)(row * HPITCH + seg * 8) * 2;
            *(uint4*)(dynsm + WS_H + dst) = *(const uint4*)(whH + src);
            *(uint4*)(dynsm + WS_L + dst) = *(const uint4*)(whL + src);
        }
    }

    // Cell state: thread (b, ul) with b = tid>>2, ul = tid&3.
    const int bT = tid >> 2, ulT = tid & 3;
    float cv = c0l[bT * H + u0 + ulT];
    __syncthreads();

    // ldmatrix lane bases (same mapping as gemm_hmma, proven)
    const int sel = lane >> 3, lr = lane & 7;
    const uint32_t aRow = (uint32_t)(wm * 16 + (sel & 1) * 8 + lr);
    const uint32_t aCol = (uint32_t)((sel >> 1) * 8);
    const uint32_t aOffH = sb + HS_H + (aRow * HPITCH + wk * 256 + aCol) * 2;
    const uint32_t aOffL = sb + HS_L + (aRow * HPITCH + wk * 256 + aCol) * 2;
    const uint32_t bRow = (uint32_t)lr;
    const uint32_t bCol = (uint32_t)((sel & 1) * 8);
    const uint32_t bOffH = sb + WS_H + (bRow * HPITCH + wk * 256 + bCol) * 2;
    const uint32_t bOffL = sb + WS_L + (bRow * HPITCH + wk * 256 + bCol) * 2;

    float* xs   = (float*)(dynsm + XS_OFF);
    float* gred = (float*)(dynsm + GR_OFF);

    for (int t = 0; t < S; t++) {
        const int rbuf = (t + 1) & 1, wbuf = t & 1;

        // xg prefetch into smem (one float4 per thread)
        {
            const float4 xv = *(const float4*)(
                g_xg + (size_t)t * B * G + bT * G + ulT * 512 + u0);
            *(float4*)(&xs[bT * 16 + ulT * 4]) = xv;    // cols gate*4..gate*4+3
        }
        // Stage h (bf16 hi/lo) via cp.async.cg (L2-coherent across CTAs)
        {
            const __nv_bfloat16* srcH = g_hbf[rbuf][0];
            const __nv_bfloat16* srcL = g_hbf[rbuf][1];
#pragma unroll
            for (int p = 0; p < 16; p++) {
                const int f = tid + p * NTHR;       // 4096 segs per tile
                const int row = f >> 6, seg = f & 63;
                const uint32_t dst = (uint32_t)(row * HPITCH + seg * 8) * 2;
                const size_t src = (size_t)row * 512 + seg * 8;
                CPASYNC(sb + HS_H + dst, srcH + src);
                CPASYNC(sb + HS_L + dst, srcL + src);
            }
            CPCOMMIT();
            CPWAIT(0);
        }
        __syncthreads();

        // 16 k-steps x (AhBh + AhBl + AlBh) x 2 n-subtiles
        float d0[2][4] = {}, d1[2][4] = {}, d2[2][4] = {};
#pragma unroll
        for (int ks = 0; ks < 16; ks++) {
            uint32_t ah[4], al[4], bh[2][2], bl[2][2];
            LDSM4(ah[0], ah[1], ah[2], ah[3], aOffH + ks * 32);
            LDSM4(al[0], al[1], al[2], al[3], aOffL + ks * 32);
            LDSM2(bh[0][0], bh[0][1], bOffH + ks * 32);
            LDSM2(bh[1][0], bh[1][1], bOffH + 8 * HPITCH * 2 + ks * 32);
            LDSM2(bl[0][0], bl[0][1], bOffL + ks * 32);
            LDSM2(bl[1][0], bl[1][1], bOffL + 8 * HPITCH * 2 + ks * 32);
#pragma unroll
            for (int j = 0; j < 2; j++) {
                MMA16816(d0[j], ah, bh[j]);
                MMA16816(d1[j], ah, bl[j]);
                MMA16816(d2[j], al, bh[j]);
            }
        }
        float dd[2][4];
#pragma unroll
        for (int j = 0; j < 2; j++)
#pragma unroll
            for (int q = 0; q < 4; q++)
                dd[j][q] = (d0[j][q] + d1[j][q]) + d2[j][q];

        // k-split reduction through gred[64][18]
        const int gq = lane >> 2, tq = lane & 3;
        if (wk == 1) {
#pragma unroll
            for (int j = 0; j < 2; j++) {
                *(float2*)(&gred[(wm * 16 + gq) * 18 + j * 8 + tq * 2]) =
                    make_float2(dd[j][0], dd[j][1]);
                *(float2*)(&gred[(wm * 16 + gq + 8) * 18 + j * 8 + tq * 2]) =
                    make_float2(dd[j][2], dd[j][3]);
            }
        }
        __syncthreads();
        if (wk == 0) {
#pragma unroll
            for (int j = 0; j < 2; j++) {
                float2* p0 = (float2*)(&gred[(wm * 16 + gq) * 18 + j * 8 + tq * 2]);
                float2* p1 = (float2*)(&gred[(wm * 16 + gq + 8) * 18 + j * 8 + tq * 2]);
                float2 v0 = *p0, v1 = *p1;
                v0.x += dd[j][0]; v0.y += dd[j][1];
                v1.x += dd[j][2]; v1.y += dd[j][3];
                *p0 = v0; *p1 = v1;
            }
        }
        __syncthreads();

        // Elementwise update: thread (bT, ulT)
        {
            const int u = u0 + ulT;
            const float gi = gred[bT * 18 +  0 + ulT] + xs[bT * 16 +  0 + ulT];
            const float gf = gred[bT * 18 +  4 + ulT] + xs[bT * 16 +  4 + ulT];
            const float go = gred[bT * 18 +  8 + ulT] + xs[bT * 16 +  8 + ulT];
            const float gg = gred[bT * 18 + 12 + ulT] + xs[bT * 16 + 12 + ulT];
            const float i_ = __fdividef(1.f, 1.f + __expf(-gi));
            const float f_ = __fdividef(1.f, 1.f + __expf(-gf));
            const float o_ = __fdividef(1.f, 1.f + __expf(-go));
            const float gv = tanhf(gg);
            cv = f_ * cv + i_ * gv;
            const float hnew = o_ * tanhf(cv);

            __nv_bfloat16 hh, hl;
            bsplit(hnew, hh, hl);
            g_hbf[wbuf][0][bT * H + u] = hh;
            g_hbf[wbuf][1][bT * H + u] = hl;

            if (layer == 0) {
                const size_t o = ((size_t)t * B + bT) * 512 + u;
                g_y1h[o] = hh;
                g_y1l[o] = hl;
            } else {
                dout[(size_t)bT * S * H + (size_t)t * H + u] = hnew;
            }
            if (t == S - 1) {
                const size_t BSH = (size_t)B * S * H, BH = (size_t)B * H;
                dout[BSH + (size_t)layer * BH + bT * H + u] = hnew;
                dout[BSH + 2 * BH + (size_t)layer * BH + bT * H + u] = cv;
            }
        }

        // Grid-wide barrier between steps
        if (t != S - 1) {
            __threadfence();
            __syncthreads();
            if (tid == 0) {
                atomicAdd((unsigned*)bar, 1u);
                const unsigned tgt = (unsigned)(t + 1) * NCTA;
                while (*bar < tgt) { }     // monotonic: no reset race
            }
            __syncthreads();
        }
    }
}

// ---------------------------------------------------------------------------
// Launch: split_x, split_w; per layer: GEMM, init_h, persistent recurrence.
// 8 graph nodes. No allocs, no syncs, graph-capturable.
// ---------------------------------------------------------------------------
extern "C" void kernel_launch(void* const* d_in, const int* in_sizes, int n_in,
                              void* d_out, int out_size)
{
    const float* x  = (const float*)d_in[0];
    const float* W  = (const float*)d_in[1];
    const float* bb = (const float*)d_in[2];
    const float* h0 = (const float*)d_in[3];
    const float* c0 = (const float*)d_in[4];
    float* out = (float*)d_out;

    cudaFuncSetAttribute(gemm_hmma, cudaFuncAttributeMaxDynamicSharedMemorySize, GSMEM);
    cudaFuncSetAttribute(lstm_persist, cudaFuncAttributeMaxDynamicSharedMemorySize, P2_SMEM);

    split_x<<<(M_TOT * 512 / 4) / 256, 256>>>(x);
    split_w<<<(2 * G * WROW / 4) / 256, 256>>>(W);

    for (int layer = 0; layer < 2; layer++) {
        gemm_hmma<<<dim3(16, 512), 256, GSMEM>>>(bb + layer * G, layer);
        init_h<<<(B * H) / 256, 256>>>(h0 + (size_t)layer * B * H);
        lstm_persist<<<NCTA, NTHR, P2_SMEM>>>(layer, c0 + (size_t)layer * B * H, out);
    }
}

// round 10
// speedup vs baseline: 1.9334x; 1.1186x over previous
#include <cuda_runtime.h>
#include <cuda_bf16.h>
#include <math.h>
#include <cstdint>

// Problem constants
#define B    64
#define S    1024
#define D    512
#define H    512
#define G    2048      // 4*H
#define WROW 1024      // D+H, row stride of W
#define M_TOT (S*B)    // 65536 GEMM rows, m = t*B + b
#define NCTA 128
#define NTHR 256

// ---------------------------------------------------------------------------
// Scratch (__device__ globals: sanctioned alloc-free workaround)
// ---------------------------------------------------------------------------
__device__ __nv_bfloat16 g_xh [(size_t)M_TOT * 512];     // layer-0 A hi
__device__ __nv_bfloat16 g_xl [(size_t)M_TOT * 512];     // layer-0 A lo
__device__ __nv_bfloat16 g_y1h[(size_t)M_TOT * 512];     // layer-1 A hi
__device__ __nv_bfloat16 g_y1l[(size_t)M_TOT * 512];     // layer-1 A lo
__device__ __nv_bfloat16 g_wh [2 * (size_t)G * WROW];    // W hi, [layer][n][WROW]
__device__ __nv_bfloat16 g_wl [2 * (size_t)G * WROW];    // W lo
__device__ float g_xg[(size_t)S * B * G];                // input gates (t*B+b, G)
__device__ __nv_bfloat16 g_hbf[2][2][B * H];             // ping-pong h, [buf][hi/lo]
__device__ unsigned g_bar[2];                            // grid-barrier counters

// ---------------------------------------------------------------------------
// PTX helpers (arch-portable: sm_80+ only)
// ---------------------------------------------------------------------------
__device__ __forceinline__ uint32_t smem_u32(const void* p) {
    uint32_t a;
    asm("{ .reg .u64 t; cvta.to.shared.u64 t, %1; cvt.u32.u64 %0, t; }"
        : "=r"(a) : "l"(p));
    return a;
}

#define CPASYNC(sm, gm) \
    asm volatile("cp.async.cg.shared.global [%0], [%1], 16;" :: "r"(sm), "l"(gm))
#define CPCOMMIT() asm volatile("cp.async.commit_group;" ::: "memory")
#define CPWAIT(n)  asm volatile("cp.async.wait_group %0;" :: "n"(n) : "memory")

#define LDSM4(r0, r1, r2, r3, addr) \
    asm volatile("ldmatrix.sync.aligned.m8n8.x4.shared.b16 {%0,%1,%2,%3}, [%4];" \
        : "=r"(r0), "=r"(r1), "=r"(r2), "=r"(r3) : "r"(addr))
#define LDSM2(r0, r1, addr) \
    asm volatile("ldmatrix.sync.aligned.m8n8.x2.shared.b16 {%0,%1}, [%2];" \
        : "=r"(r0), "=r"(r1) : "r"(addr))

#define MMA16816(d, a, b) \
    asm volatile("mma.sync.aligned.m16n8k16.row.col.f32.bf16.bf16.f32 " \
        "{%0,%1,%2,%3},{%4,%5,%6,%7},{%8,%9},{%0,%1,%2,%3};" \
        : "+f"((d)[0]), "+f"((d)[1]), "+f"((d)[2]), "+f"((d)[3]) \
        : "r"((a)[0]), "r"((a)[1]), "r"((a)[2]), "r"((a)[3]), \
          "r"((b)[0]), "r"((b)[1]))

__device__ __forceinline__ void bsplit(float v, __nv_bfloat16& h, __nv_bfloat16& l) {
    h = __float2bfloat16(v);
    l = __float2bfloat16(v - __bfloat162float(h));
}

// ---------------------------------------------------------------------------
// Split kernels: fp32 -> bf16 hi/lo
// ---------------------------------------------------------------------------
__global__ void __launch_bounds__(256) split_x(const float* __restrict__ x)
{
    const size_t i4 = (size_t)blockIdx.x * 256 + threadIdx.x;  // over M_TOT*512/4
    const float4 v = ((const float4*)x)[i4];
    const size_t idx = i4 * 4;                 // (b, t, k) in x layout
    const int k = (int)(idx & 511);
    const int t = (int)((idx >> 9) & 1023);
    const int b = (int)(idx >> 19);
    const size_t o = ((size_t)t * B + b) * 512 + k;   // GEMM A layout (m, k)
    __nv_bfloat16 h0, l0, h1, l1, h2, l2, h3, l3;
    bsplit(v.x, h0, l0); bsplit(v.y, h1, l1);
    bsplit(v.z, h2, l2); bsplit(v.w, h3, l3);
    __nv_bfloat162 a, bb2;
    a.x = h0; a.y = h1; bb2.x = h2; bb2.y = h3;
    *(__nv_bfloat162*)(g_xh + o)     = a;
    *(__nv_bfloat162*)(g_xh + o + 2) = bb2;
    a.x = l0; a.y = l1; bb2.x = l2; bb2.y = l3;
    *(__nv_bfloat162*)(g_xl + o)     = a;
    *(__nv_bfloat162*)(g_xl + o + 2) = bb2;
}

// Full-W split: source layout [layer][n][WROW] is copied linearly.
__global__ void __launch_bounds__(256) split_w(const float* __restrict__ W)
{
    const size_t i4 = (size_t)blockIdx.x * 256 + threadIdx.x;  // over 2*G*WROW/4
    const float4 v = ((const float4*)W)[i4];
    const size_t idx = i4 * 4;
    __nv_bfloat16 h0, l0, h1, l1, h2, l2, h3, l3;
    bsplit(v.x, h0, l0); bsplit(v.y, h1, l1);
    bsplit(v.z, h2, l2); bsplit(v.w, h3, l3);
    __nv_bfloat162 a, bb2;
    a.x = h0; a.y = h1; bb2.x = h2; bb2.y = h3;
    *(__nv_bfloat162*)(g_wh + idx)     = a;
    *(__nv_bfloat162*)(g_wh + idx + 2) = bb2;
    a.x = l0; a.y = l1; bb2.x = l2; bb2.y = l3;
    *(__nv_bfloat162*)(g_wl + idx)     = a;
    *(__nv_bfloat162*)(g_wl + idx + 2) = bb2;
}

// Convert h0 (fp32) into the bf16 ping-pong buffer read at t=0 (index 1).
__global__ void __launch_bounds__(256) init_h(const float* __restrict__ h0l)
{
    const int i = blockIdx.x * 256 + threadIdx.x;   // 0..B*H-1
    __nv_bfloat16 hh, hl;
    bsplit(h0l[i], hh, hl);
    g_hbf[1][0][i] = hh;
    g_hbf[1][1][i] = hl;
}

// ---------------------------------------------------------------------------
// HMMA bf16-split GEMM: xg[m][n] = sum_k A[m][k]*Wx[n][k] + bias[n]
// (unchanged from R8 — proven)
// ---------------------------------------------------------------------------
#define APITCH 72
#define ATILEB (128 * APITCH * 2)        // 18432 B per operand tile
#define STAGEB (2 * ATILEB)              // A + B per stage
#define GSMEM  (2 * STAGEB)              // double buffered = 73728 B

__global__ void __launch_bounds__(256) gemm_hmma(
    const float* __restrict__ bias, int layer)
{
    if (blockIdx.x == 0 && blockIdx.y == 0 && threadIdx.x == 0)
        g_bar[layer] = 0u;               // reset grid barrier for this layer

    const __nv_bfloat16* __restrict__ Ah = layer ? g_y1h : g_xh;
    const __nv_bfloat16* __restrict__ Al = layer ? g_y1l : g_xl;
    const __nv_bfloat16* __restrict__ Bh = g_wh + (size_t)layer * G * WROW;
    const __nv_bfloat16* __restrict__ Bl = g_wl + (size_t)layer * G * WROW;
    const __nv_bfloat16* APs[3] = { Ah, Ah, Al };
    const __nv_bfloat16* BPs[3] = { Bh, Bl, Bh };

    extern __shared__ char dynsm[];
    const uint32_t sbase = smem_u32(dynsm);
    const int tid = threadIdx.x, lane = tid & 31, warp = tid >> 5;
    const int wm = warp & 1, wn = warp >> 1;          // warp grid 2(M) x 4(N)
    const int m0 = blockIdx.y * 128, n0 = blockIdx.x * 128;

    const int sel = lane >> 3, lr = lane & 7;
    const uint32_t aRow  = wm * 64 + (sel & 1) * 8 + lr;
    const uint32_t aColB = (sel >> 1) * 8;
    const uint32_t bRow  = wn * 32 + lr;
    const uint32_t bColB = (sel & 1) * 8;

    float d[4][4][4];
#pragma unroll
    for (int i = 0; i < 4; i++)
#pragma unroll
        for (int j = 0; j < 4; j++)
#pragma unroll
            for (int q = 0; q < 4; q++) d[i][j][q] = 0.0f;

    auto issue = [&](int c, int buf) {
        const int term = c >> 3, kg = (c & 7) * 64;
        const __nv_bfloat16* Ap = APs[term];
        const __nv_bfloat16* Bp = BPs[term];
        const uint32_t sA = sbase + buf * STAGEB;
        const uint32_t sB = sA + ATILEB;
#pragma unroll
        for (int p = 0; p < 4; p++) {
            const int f = tid + p * 256;
            const int row = f >> 3, seg = f & 7;
            const uint32_t so = (uint32_t)(row * APITCH + seg * 8) * 2;
            CPASYNC(sA + so, Ap + (size_t)(m0 + row) * 512 + kg + seg * 8);
            CPASYNC(sB + so, Bp + (size_t)(n0 + row) * WROW + kg + seg * 8);
        }
        CPCOMMIT();
    };

    issue(0, 0);
    for (int c = 0; c < 24; c++) {
        const int buf = c & 1;
        if (c + 1 < 24) { issue(c + 1, buf ^ 1); CPWAIT(1); }
        else            { CPWAIT(0); }
        __syncthreads();

        const uint32_t sA = sbase + buf * STAGEB;
        const uint32_t sB = sA + ATILEB;
        const uint32_t aBase = sA + (aRow * APITCH + aColB) * 2;
        const uint32_t bBase = sB + (bRow * APITCH + bColB) * 2;

#pragma unroll
        for (int ks = 0; ks < 4; ks++) {
            uint32_t a[4][4], b[4][2];
#pragma unroll
            for (int i = 0; i < 4; i++)
                LDSM4(a[i][0], a[i][1], a[i][2], a[i][3],
                      aBase + (uint32_t)(i * 16 * APITCH + ks * 16) * 2);
#pragma unroll
            for (int j = 0; j < 4; j++)
                LDSM2(b[j][0], b[j][1],
                      bBase + (uint32_t)(j * 8 * APITCH + ks * 16) * 2);
#pragma unroll
            for (int i = 0; i < 4; i++)
#pragma unroll
                for (int j = 0; j < 4; j++)
                    MMA16816(d[i][j], a[i], b[j]);
        }
        __syncthreads();
    }

    const int gq = lane >> 2, tq = lane & 3;
#pragma unroll
    for (int i = 0; i < 4; i++) {
#pragma unroll
        for (int j = 0; j < 4; j++) {
            const int col = n0 + wn * 32 + j * 8 + tq * 2;
            const int row0 = m0 + wm * 64 + i * 16 + gq;
            const float b0 = bias[col], b1 = bias[col + 1];
            float2 v0, v1;
            v0.x = d[i][j][0] + b0; v0.y = d[i][j][1] + b1;
            v1.x = d[i][j][2] + b0; v1.y = d[i][j][3] + b1;
            *(float2*)(g_xg + (size_t)row0 * G + col) = v0;
            *(float2*)(g_xg + (size_t)(row0 + 8) * G + col) = v1;
        }
    }
}

// ---------------------------------------------------------------------------
// Persistent HMMA recurrence, v2:
//  - per-warp self-staging of its own h region (disjoint) -> no stage sync
//  - xg via cp.async in its own group, waited only before elementwise
//  - B via LDSM4 (4 ldmatrix/ks instead of 6)
//  - single-pass gred (both k-halves store; elementwise adds) -> 1 sync
//  - release/acquire grid barrier (no threadfence/CCTL.IVALL)
// ---------------------------------------------------------------------------
#define HPITCH 520                       // halves per row: 1040 B
#define HS_H   0
#define HS_L   (HS_H + 64 * HPITCH * 2)      // 66560
#define WS_H   (HS_L + 64 * HPITCH * 2)      // 133120
#define WS_L   (WS_H + 16 * HPITCH * 2)      // 149760
#define XS_OFF (WS_L + 16 * HPITCH * 2)      // 166400, [64][16] fp32
#define GR_OFF (XS_OFF + 64 * 16 * 4)        // 170496, [2][64][18] fp32
#define P2_SMEM (GR_OFF + 2 * 64 * 18 * 4)   // 179712 B

__global__ void __launch_bounds__(NTHR, 1) lstm_persist(
    int layer,
    const float* __restrict__ c0l,
    float* __restrict__ dout)
{
    extern __shared__ char dynsm[];
    const uint32_t sb = smem_u32(dynsm);
    const int tid = threadIdx.x, lane = tid & 31, warp = tid >> 5;
    const int wm = warp & 3;            // m-tile: batches [wm*16, wm*16+16)
    const int wk = warp >> 2;           // k-half: k in [wk*256, wk*256+256)
    const int u0 = blockIdx.x * 4;
    unsigned* bar = &g_bar[layer];

    // --- Stage Wh rows (16 x 512, hi/lo) into smem once. Row n = gate*4+uu.
    {
        const __nv_bfloat16* whH = g_wh + (size_t)layer * G * WROW;
        const __nv_bfloat16* whL = g_wl + (size_t)layer * G * WROW;
#pragma unroll
        for (int p = 0; p < 4; p++) {
            const int f = tid + p * NTHR;          // 1024 segs per tile
            const int row = f >> 6, seg = f & 63;
            const int g = row >> 2, uu = row & 3;
            const size_t src = (size_t)(g * 512 + u0 + uu) * WROW + 512 + seg * 8;
            const uint32_t dst = (uint32_t)(row * HPITCH + seg * 8) * 2;
            *(uint4*)(dynsm + WS_H + dst) = *(const uint4*)(whH + src);
            *(uint4*)(dynsm + WS_L + dst) = *(const uint4*)(whL + src);
        }
    }

    // Cell state: thread (b, ul) with b = tid>>2, ul = tid&3.
    const int bT = tid >> 2, ulT = tid & 3;
    float cv = c0l[bT * H + u0 + ulT];
    __syncthreads();

    // ldmatrix lane bases (A mapping proven in gemm_hmma; B uses x4 variant)
    const int sel = lane >> 3, lr = lane & 7;
    const uint32_t aRow = (uint32_t)(wm * 16 + (sel & 1) * 8 + lr);
    const uint32_t aCol = (uint32_t)((sel >> 1) * 8);
    const uint32_t aOffH = sb + HS_H + (aRow * HPITCH + wk * 256 + aCol) * 2;
    const uint32_t aOffL = sb + HS_L + (aRow * HPITCH + wk * 256 + aCol) * 2;
    // B x4: m0=(n lr,k0) m1=(n lr,k8) m2=(n lr+8,k0) m3=(n lr+8,k8)
    const uint32_t bRow = (uint32_t)(lr + (sel >> 1) * 8);
    const uint32_t bCol = (uint32_t)((sel & 1) * 8);
    const uint32_t bOffH = sb + WS_H + (bRow * HPITCH + wk * 256 + bCol) * 2;
    const uint32_t bOffL = sb + WS_L + (bRow * HPITCH + wk * 256 + bCol) * 2;

    float* xs   = (float*)(dynsm + XS_OFF);
    float* gred = (float*)(dynsm + GR_OFF);

    // Per-warp h-stage bases (each warp stages its own disjoint region)
    const uint32_t stHd = sb + HS_H + ((uint32_t)(wm * 16) * HPITCH + wk * 256) * 2 + lane * 16;
    const uint32_t stLd = sb + HS_L + ((uint32_t)(wm * 16) * HPITCH + wk * 256) * 2 + lane * 16;
    const size_t   stSrc = (size_t)(wm * 16) * 512 + wk * 256 + lane * 8;

    for (int t = 0; t < S; t++) {
        const int rbuf = (t + 1) & 1, wbuf = t & 1;

        // Group 1: h stage (own warp's 16 rows x 256 halves, hi+lo)
        {
            const __nv_bfloat16* srcH = g_hbf[rbuf][0] + stSrc;
            const __nv_bfloat16* srcL = g_hbf[rbuf][1] + stSrc;
#pragma unroll
            for (int i = 0; i < 16; i++) {
                CPASYNC(stHd + (uint32_t)(i * HPITCH) * 2, srcH + (size_t)i * 512);
                CPASYNC(stLd + (uint32_t)(i * HPITCH) * 2, srcL + (size_t)i * 512);
            }
            CPCOMMIT();
        }
        // Group 2 (newest): xg -> xs (DRAM; waited only before elementwise)
        CPASYNC(sb + XS_OFF + (uint32_t)(bT * 16 + ulT * 4) * 4,
                g_xg + (size_t)t * B * G + bT * G + ulT * 512 + u0);
        CPCOMMIT();

        CPWAIT(1);        // wait h group only (xg still pending)
        __syncwarp();

        // 16 k-steps x (AhBh -> main, AhBl + AlBh -> corr)
        float dm[2][4] = {}, dc[2][4] = {};
#pragma unroll
        for (int ks = 0; ks < 16; ks++) {
            uint32_t ah[4], al[4], bh[4], bl[4];
            LDSM4(ah[0], ah[1], ah[2], ah[3], aOffH + ks * 32);
            LDSM4(al[0], al[1], al[2], al[3], aOffL + ks * 32);
            LDSM4(bh[0], bh[1], bh[2], bh[3], bOffH + ks * 32);
            LDSM4(bl[0], bl[1], bl[2], bl[3], bOffL + ks * 32);
            MMA16816(dm[0], ah, bh);
            MMA16816(dm[1], ah, bh + 2);
            MMA16816(dc[0], ah, bl);
            MMA16816(dc[1], ah, bl + 2);
            MMA16816(dc[0], al, bh);
            MMA16816(dc[1], al, bh + 2);
        }

        // Both k-halves store partials; elementwise adds them.
        {
            const int gq = lane >> 2, tq = lane & 3;
            float* gr = gred + wk * (64 * 18);
#pragma unroll
            for (int j = 0; j < 2; j++) {
                *(float2*)(&gr[(wm * 16 + gq) * 18 + j * 8 + tq * 2]) =
                    make_float2(dm[j][0] + dc[j][0], dm[j][1] + dc[j][1]);
                *(float2*)(&gr[(wm * 16 + gq + 8) * 18 + j * 8 + tq * 2]) =
                    make_float2(dm[j][2] + dc[j][2], dm[j][3] + dc[j][3]);
            }
        }
        __syncthreads();

        // Elementwise update: thread (bT, ulT)
        {
            CPWAIT(0);        // xg group done (long since, behind mma)
            __syncwarp();
            const int u = u0 + ulT;
            const float gi = gred[bT * 18 +  0 + ulT] + gred[64 * 18 + bT * 18 +  0 + ulT]
                           + xs[bT * 16 +  0 + ulT];
            const float gf = gred[bT * 18 +  4 + ulT] + gred[64 * 18 + bT * 18 +  4 + ulT]
                           + xs[bT * 16 +  4 + ulT];
            const float go = gred[bT * 18 +  8 + ulT] + gred[64 * 18 + bT * 18 +  8 + ulT]
                           + xs[bT * 16 +  8 + ulT];
            const float gg = gred[bT * 18 + 12 + ulT] + gred[64 * 18 + bT * 18 + 12 + ulT]
                           + xs[bT * 16 + 12 + ulT];
            const float i_ = __fdividef(1.f, 1.f + __expf(-gi));
            const float f_ = __fdividef(1.f, 1.f + __expf(-gf));
            const float o_ = __fdividef(1.f, 1.f + __expf(-go));
            const float gv = tanhf(gg);
            cv = f_ * cv + i_ * gv;
            const float hnew = o_ * tanhf(cv);

            __nv_bfloat16 hh, hl;
            bsplit(hnew, hh, hl);
            g_hbf[wbuf][0][bT * H + u] = hh;
            g_hbf[wbuf][1][bT * H + u] = hl;

            if (layer == 0) {
                const size_t o = ((size_t)t * B + bT) * 512 + u;
                g_y1h[o] = hh;
                g_y1l[o] = hl;
            } else {
                dout[(size_t)bT * S * H + (size_t)t * H + u] = hnew;
            }
            if (t == S - 1) {
                const size_t BSH = (size_t)B * S * H, BH = (size_t)B * H;
                dout[BSH + (size_t)layer * BH + bT * H + u] = hnew;
                dout[BSH + 2 * BH + (size_t)layer * BH + bT * H + u] = cv;
            }
        }

        // Grid-wide barrier between steps (release/acquire; no L1 flush)
        if (t != S - 1) {
            __syncthreads();
            if (tid == 0) {
                asm volatile("red.release.gpu.add.u32 [%0], %1;"
                             :: "l"(bar), "r"(1u) : "memory");
                const unsigned tgt = (unsigned)(t + 1) * NCTA;
                unsigned v;
                do {
                    asm volatile("ld.acquire.gpu.u32 %0, [%1];"
                                 : "=r"(v) : "l"(bar) : "memory");
                } while (v < tgt);
            }
            __syncthreads();
        }
    }
}

// ---------------------------------------------------------------------------
// Launch: split_x, split_w; per layer: GEMM, init_h, persistent recurrence.
// 8 graph nodes. No allocs, no syncs, graph-capturable.
// ---------------------------------------------------------------------------
extern "C" void kernel_launch(void* const* d_in, const int* in_sizes, int n_in,
                              void* d_out, int out_size)
{
    const float* x  = (const float*)d_in[0];
    const float* W  = (const float*)d_in[1];
    const float* bb = (const float*)d_in[2];
    const float* h0 = (const float*)d_in[3];
    const float* c0 = (const float*)d_in[4];
    float* out = (float*)d_out;

    cudaFuncSetAttribute(gemm_hmma, cudaFuncAttributeMaxDynamicSharedMemorySize, GSMEM);
    cudaFuncSetAttribute(lstm_persist, cudaFuncAttributeMaxDynamicSharedMemorySize, P2_SMEM);

    split_x<<<(M_TOT * 512 / 4) / 256, 256>>>(x);
    split_w<<<(2 * G * WROW / 4) / 256, 256>>>(W);

    for (int layer = 0; layer < 2; layer++) {
        gemm_hmma<<<dim3(16, 512), 256, GSMEM>>>(bb + layer * G, layer);
        init_h<<<(B * H) / 256, 256>>>(h0 + (size_t)layer * B * H);
        lstm_persist<<<NCTA, NTHR, P2_SMEM>>>(layer, c0 + (size_t)layer * B * H, out);
    }
}